// round 3
// baseline (speedup 1.0000x reference)
#include <cuda_runtime.h>

// SSD detection post-processing, B=128, N=8732, C=21, top_k=keep_top_k=200.
// K1: softmax -> order-mapped scores.  K2: per-(b,cls) exact top-200 (radix
// select, warp-private hists, parallel suffix scan) + decode of selected boxes
// + suppression-bitmatrix NMS (no per-iteration barriers).  K3: global top-200
// + per-class compaction.

#define NB   128
#define NA   8732
#define NCLS 21
#define NC1  20
#define TK   200
#define NCAP 224   // padded candidate capacity (7 words of 32)

// ---- scratch (device globals; no allocation allowed) ----
__device__ unsigned int g_umap[(size_t)NB * NC1 * NA];
__device__ float        g_kscore[NB * NC1 * TK];
__device__ float4       g_kbox[NB * NC1 * TK];

// orderable map: ascending uint <=> ascending float
__device__ __forceinline__ unsigned f2u(float f) {
    unsigned b = __float_as_uint(f);
    return (b & 0x80000000u) ? ~b : (b | 0x80000000u);
}
__device__ __forceinline__ float u2f(unsigned u) {
    unsigned b = (u & 0x80000000u) ? (u & 0x7FFFFFFFu) : ~u;
    return __uint_as_float(b);
}

// ============================================================================
// K1: softmax over 21 classes -> order-mapped thresholded scores
// ============================================================================
__global__ __launch_bounds__(256) void k_prep(const float* __restrict__ conf)
{
    __shared__ float s_conf[256 * NCLS];
    int b   = blockIdx.y;
    int n0  = blockIdx.x * 256;
    int tid = threadIdx.x;

    int nrow = NA - n0; if (nrow > 256) nrow = 256;
    int cnt  = nrow * NCLS;
    size_t base = ((size_t)b * NA + n0) * NCLS;
    for (int i = tid; i < cnt; i += 256) s_conf[i] = conf[base + i];
    __syncthreads();

    int n = n0 + tid;
    if (n >= NA) return;

    const float* cv = &s_conf[tid * NCLS];
    float m = cv[0];
#pragma unroll
    for (int c = 1; c < NCLS; c++) m = fmaxf(m, cv[c]);
    float e[NCLS];
    float s = 0.f;
#pragma unroll
    for (int c = 0; c < NCLS; c++) { e[c] = expf(__fsub_rn(cv[c], m)); s = __fadd_rn(s, e[c]); }
#pragma unroll
    for (int c = 1; c < NCLS; c++) {
        float p  = __fdiv_rn(e[c], s);
        float sv = (p > 0.01f) ? p : -1.0f;
        g_umap[((size_t)b * NC1 + (c - 1)) * NA + n] = f2u(sv);
    }
}

// ============================================================================
// K2: per (batch,class): exact top-200 + decode + bitmatrix greedy NMS
// grid: NB*NC1 blocks, 256 threads
// ============================================================================
__global__ __launch_bounds__(256) void k_sel(const float* __restrict__ loc,
                                             const float* __restrict__ dbox)
{
    __shared__ __align__(16) unsigned s_u[NA];          // 34928 B (reused for boxes)
    __shared__ unsigned long long    s_cand[256];       // 2048 B
    __shared__ unsigned              s_hist[8][257];    // 8224 B (bank-padded; reused: s_mat)
    __shared__ unsigned              s_cnt[256];        // 1024 B
    __shared__ unsigned              s_aw[8];
    __shared__ unsigned              s_info[4];

    int task = blockIdx.x;               // b*20 + c
    int b    = task / NC1;
    int tid  = threadIdx.x;
    int wid  = tid >> 5, lane = tid & 31;

    // ---- load score row (vectorized; 8732 % 4 == 0) ----
    const uint4* urow = reinterpret_cast<const uint4*>(&g_umap[(size_t)task * NA]);
    uint4* su4 = reinterpret_cast<uint4*>(s_u);
    for (int i = tid; i < NA / 4; i += 256) su4[i] = urow[i];
    __syncthreads();

    // ---- 4-level radix select (warp-private hists + parallel suffix scan) ----
    unsigned prefix = 0, k = TK;
#pragma unroll
    for (int level = 0; level < 4; level++) {
        int shift = 24 - 8 * level;
        unsigned mask = (level == 0) ? 0u : (0xFFFFFFFFu << (32 - 8 * level));
        for (int i = tid; i < 8 * 257; i += 256) (&s_hist[0][0])[i] = 0;
        __syncthreads();
        for (int i = tid; i < NA; i += 256) {
            unsigned u = s_u[i];
            if ((u & mask) == prefix) atomicAdd(&s_hist[wid][(u >> shift) & 255], 1u);
        }
        __syncthreads();
        unsigned c = 0;
#pragma unroll
        for (int w = 0; w < 8; w++) c += s_hist[w][tid];
        unsigned v = c;
        s_cnt[tid] = v;
        __syncthreads();
#pragma unroll
        for (int off = 1; off < 256; off <<= 1) {
            unsigned add = (tid + off < 256) ? s_cnt[tid + off] : 0u;
            __syncthreads();
            v += add; s_cnt[tid] = v;
            __syncthreads();
        }
        unsigned excl = v - c;                     // count strictly above bin tid
        if (excl < k && v >= k) {
            s_info[0] = prefix | ((unsigned)tid << shift);
            s_info[1] = k - excl;
        }
        __syncthreads();
        prefix = s_info[0];
        k      = s_info[1];
        __syncthreads();
    }
    unsigned ucut = prefix, keq = k;

    // ---- gather exactly 200 candidates ----
    if (tid == 0) { s_info[2] = 0; s_info[3] = 0; }
    __syncthreads();
    for (int i = tid; i < NA; i += 256) {
        unsigned u = s_u[i];
        if (u > ucut) {
            unsigned p = atomicAdd(&s_info[2], 1u);
            s_cand[p] = ((unsigned long long)u << 32) | (0xFFFFFFFFu - (unsigned)i);
        }
    }
    __syncthreads();
    unsigned ngt = s_info[2];
    for (int i = tid; i < NA; i += 256) {
        unsigned u = s_u[i];
        if (u == ucut) {
            unsigned p = atomicAdd(&s_info[3], 1u);
            if (p < keq)
                s_cand[ngt + p] = ((unsigned long long)u << 32) | (0xFFFFFFFFu - (unsigned)i);
        }
    }
    __syncthreads();
    if (tid >= TK) s_cand[tid] = 0ULL;
    __syncthreads();

    // ---- bitonic sort 256 keys desc (value desc, index asc on ties) ----
    for (int kk = 2; kk <= 256; kk <<= 1) {
        for (int j = kk >> 1; j > 0; j >>= 1) {
            int ixj = tid ^ j;
            if (ixj > tid) {
                unsigned long long a = s_cand[tid], c2 = s_cand[ixj];
                bool dir = ((tid & kk) == 0);
                if ((a < c2) == dir) { s_cand[tid] = c2; s_cand[ixj] = a; }
            }
            __syncthreads();
        }
    }

    // ---- stage candidates: decode selected boxes (overlay on s_u) ----
    float4* s_box   = reinterpret_cast<float4*>(s_u);           // [224]
    float*  s_area  = reinterpret_cast<float*>(s_u + 896);      // [224]
    float*  s_score = reinterpret_cast<float*>(s_u + 1120);     // [224]
    bool alive = false;
    if (tid < NCAP) {
        float v = 0.f;
        float4 bb = make_float4(0.f, 0.f, 0.f, 0.f);
        if (tid < TK) {
            unsigned long long key = s_cand[tid];
            unsigned u = (unsigned)(key >> 32);
            int idx = (int)(0xFFFFFFFFu - (unsigned)key);
            v = u2f(u);
            float4 l = reinterpret_cast<const float4*>(loc)[b * NA + idx];
            float4 d = reinterpret_cast<const float4*>(dbox)[idx];
            float cx = __fadd_rn(d.x, __fmul_rn(__fmul_rn(l.x, 0.1f), d.z));
            float cy = __fadd_rn(d.y, __fmul_rn(__fmul_rn(l.y, 0.1f), d.w));
            float w  = __fmul_rn(d.z, expf(__fmul_rn(l.z, 0.2f)));
            float h  = __fmul_rn(d.w, expf(__fmul_rn(l.w, 0.2f)));
            float x1 = __fsub_rn(cx, __fmul_rn(w, 0.5f));
            float y1 = __fsub_rn(cy, __fmul_rn(h, 0.5f));
            float x2 = __fadd_rn(x1, w);
            float y2 = __fadd_rn(y1, h);
            bb.x = fminf(fmaxf(x1, 0.f), 1.f);
            bb.y = fminf(fmaxf(y1, 0.f), 1.f);
            bb.z = fminf(fmaxf(x2, 0.f), 1.f);
            bb.w = fminf(fmaxf(y2, 0.f), 1.f);
        }
        s_box[tid]   = bb;
        s_area[tid]  = __fmul_rn(__fsub_rn(bb.z, bb.x), __fsub_rn(bb.w, bb.y));
        s_score[tid] = v;
        alive = (v > 0.01f);
    }
    unsigned ab = __ballot_sync(0xffffffffu, alive);
    if (lane == 0) s_aw[wid] = ab;
    __syncthreads();

    // ---- suppression bitmatrix: rows r<200, words w>=r>>5 (872 word-tasks) ----
    unsigned (*s_mat)[8] = reinterpret_cast<unsigned (*)[8]>(&s_hist[0][0]);
    for (int it = 0; it < 109; it++) {            // 872 = 8 warps * 109, no divergence
        int t = wid + 8 * it;
        int w = (t >= 32) + (t >= 96) + (t >= 192) + (t >= 320) + (t >= 480) + (t >= 672);
        int base = (w == 0) ? 0 : (w == 1) ? 32 : (w == 2) ? 96 : (w == 3) ? 192
                 : (w == 4) ? 320 : (w == 5) ? 480 : 672;
        int r = t - base;
        int j = w * 32 + lane;
        float4 bj = s_box[j];  float aj = s_area[j];
        float4 br = s_box[r];  float ar = s_area[r];
        float xx1 = fmaxf(bj.x, br.x);
        float yy1 = fmaxf(bj.y, br.y);
        float xx2 = fminf(bj.z, br.z);
        float yy2 = fminf(bj.w, br.w);
        float iw = fmaxf(__fsub_rn(xx2, xx1), 0.f);
        float ih = fmaxf(__fsub_rn(yy2, yy1), 0.f);
        float inter = __fmul_rn(iw, ih);
        float denom = __fsub_rn(__fadd_rn(aj, ar), inter);
        float iou   = __fdiv_rn(inter, denom);     // IEEE div; NaN -> suppress
        bool bit = (j > r) && (j < TK) && !(iou <= 0.45f);
        unsigned word = __ballot_sync(0xffffffffu, bit);
        if (lane == 0) s_mat[r][w] = word;
    }
    __syncthreads();

    // ---- greedy sweep (warp 0, register-resident alive words, no barriers) ----
    if (wid == 0) {
        unsigned a0 = s_aw[0], a1 = s_aw[1], a2 = s_aw[2], a3 = s_aw[3];
        unsigned a4 = s_aw[4], a5 = s_aw[5], a6 = s_aw[6];
#define GSTEP(S, AS, UPD)                                                   \
        for (int l2 = 0; l2 < ((32*(S)+32 <= TK) ? 32 : (TK - 32*(S))); l2++) { \
            if ((AS >> l2) & 1) {                                           \
                const unsigned* row = s_mat[32*(S) + l2];                   \
                UPD                                                         \
            }                                                               \
        }
        GSTEP(0, a0, a0&=~row[0];a1&=~row[1];a2&=~row[2];a3&=~row[3];a4&=~row[4];a5&=~row[5];a6&=~row[6];)
        GSTEP(1, a1, a1&=~row[1];a2&=~row[2];a3&=~row[3];a4&=~row[4];a5&=~row[5];a6&=~row[6];)
        GSTEP(2, a2, a2&=~row[2];a3&=~row[3];a4&=~row[4];a5&=~row[5];a6&=~row[6];)
        GSTEP(3, a3, a3&=~row[3];a4&=~row[4];a5&=~row[5];a6&=~row[6];)
        GSTEP(4, a4, a4&=~row[4];a5&=~row[5];a6&=~row[6];)
        GSTEP(5, a5, a5&=~row[5];a6&=~row[6];)
        GSTEP(6, a6, a6&=~row[6];)
#undef GSTEP
        if (lane == 0) {
            s_aw[0]=a0; s_aw[1]=a1; s_aw[2]=a2; s_aw[3]=a3;
            s_aw[4]=a4; s_aw[5]=a5; s_aw[6]=a6;
        }
    }
    __syncthreads();

    if (tid < TK) {
        bool kp = (s_aw[tid >> 5] >> (tid & 31)) & 1;
        int o = task * TK + tid;
        g_kscore[o] = kp ? s_score[tid] : 0.f;
        g_kbox[o]   = kp ? s_box[tid]  : make_float4(0.f, 0.f, 0.f, 0.f);
    }
}

// ============================================================================
// K3: per batch: global top-200 over 4000 kept scores, per-class compaction
// ============================================================================
__global__ __launch_bounds__(256) void k_final(float* __restrict__ out)
{
    __shared__ unsigned long long s_key[4096];
    int b   = blockIdx.x;
    int tid = threadIdx.x;

    const float* ks = &g_kscore[b * NC1 * TK];
    for (int i = tid; i < 4096; i += 256) {
        unsigned long long key = 0ULL;
        if (i < NC1 * TK) {
            unsigned u = f2u(ks[i]);
            key = ((unsigned long long)u << 32) | (0xFFFFFFFFu - (unsigned)i);
        }
        s_key[i] = key;
    }

    float* ob = out + (size_t)b * NCLS * TK * 5;
    for (int i = tid; i < NCLS * TK * 5; i += 256) ob[i] = 0.f;
    __syncthreads();

    for (int kk = 2; kk <= 4096; kk <<= 1) {
        for (int j = kk >> 1; j > 0; j >>= 1) {
            for (int i = tid; i < 4096; i += 256) {
                int ixj = i ^ j;
                if (ixj > i) {
                    unsigned long long a = s_key[i], c2 = s_key[ixj];
                    bool dir = ((i & kk) == 0);
                    if ((a < c2) == dir) { s_key[i] = c2; s_key[ixj] = a; }
                }
            }
            __syncthreads();
        }
    }

    if (tid < TK) {
        unsigned long long key = s_key[tid];
        unsigned u = (unsigned)(key >> 32);
        if (u > 0x80000000u) {
            unsigned flat = 0xFFFFFFFFu - (unsigned)key;
            int cls = (int)(flat / TK);
            int pos = 0;
            for (int g = 0; g < tid; g++) {
                unsigned long long k2 = s_key[g];
                unsigned u2 = (unsigned)(k2 >> 32);
                if (u2 > 0x80000000u) {
                    unsigned f2 = 0xFFFFFFFFu - (unsigned)k2;
                    if ((int)(f2 / TK) == cls) pos++;
                }
            }
            float v   = __uint_as_float(u & 0x7FFFFFFFu);
            float4 bb = g_kbox[b * NC1 * TK + flat];
            float* row = ob + ((cls + 1) * TK + pos) * 5;
            row[0] = v;
            row[1] = bb.x; row[2] = bb.y; row[3] = bb.z; row[4] = bb.w;
        }
    }
}

// ============================================================================
extern "C" void kernel_launch(void* const* d_in, const int* in_sizes, int n_in,
                              void* d_out, int out_size)
{
    const float* loc  = (const float*)d_in[0];   // [B, N, 4]
    const float* conf = (const float*)d_in[1];   // [B, N, C]
    const float* dbox = (const float*)d_in[2];   // [N, 4]
    float* out = (float*)d_out;                  // [B, C, 200, 5]

    k_prep <<<dim3((NA + 255) / 256, NB), 256>>>(conf);
    k_sel  <<<NB * NC1, 256>>>(loc, dbox);
    k_final<<<NB, 256>>>(out);
}

// round 4
// speedup vs baseline: 1.0884x; 1.0884x over previous
#include <cuda_runtime.h>

// SSD post-processing, B=128, N=8732, C=21, top_k=keep_top_k=200.
// K1 k_prep : softmax -> order-mapped thresholded scores (g_umap)
// K2 k_topk : per-(b,cls) exact top-200 via 4-level radix select reading
//             global directly (L2-resident), bitonic sort -> g_cand
// K3 k_nms  : decode selected boxes + IoU suppression bitmatrix + ffs sweep
// K4 k_final: per-batch global top-200 + per-class compaction

#define NB   128
#define NA   8732
#define NCLS 21
#define NC1  20
#define TK   200
#define NCAP 224

__device__ unsigned int       g_umap[(size_t)NB * NC1 * NA];
__device__ unsigned long long g_cand[NB * NC1 * TK];
__device__ float              g_kscore[NB * NC1 * TK];
__device__ float4             g_kbox[NB * NC1 * TK];

__device__ __forceinline__ unsigned f2u(float f) {
    unsigned b = __float_as_uint(f);
    return (b & 0x80000000u) ? ~b : (b | 0x80000000u);
}
__device__ __forceinline__ float u2f(unsigned u) {
    unsigned b = (u & 0x80000000u) ? (u & 0x7FFFFFFFu) : ~u;
    return __uint_as_float(b);
}

// ============================================================================
// K1: softmax over 21 classes -> order-mapped thresholded scores
// ============================================================================
__global__ __launch_bounds__(256) void k_prep(const float* __restrict__ conf)
{
    __shared__ float s_conf[256 * NCLS];
    int b   = blockIdx.y;
    int n0  = blockIdx.x * 256;
    int tid = threadIdx.x;

    int nrow = NA - n0; if (nrow > 256) nrow = 256;
    int cnt  = nrow * NCLS;
    size_t base = ((size_t)b * NA + n0) * NCLS;
    for (int i = tid; i < cnt; i += 256) s_conf[i] = conf[base + i];
    __syncthreads();

    int n = n0 + tid;
    if (n >= NA) return;

    const float* cv = &s_conf[tid * NCLS];
    float m = cv[0];
#pragma unroll
    for (int c = 1; c < NCLS; c++) m = fmaxf(m, cv[c]);
    float e[NCLS];
    float s = 0.f;
#pragma unroll
    for (int c = 0; c < NCLS; c++) { e[c] = expf(__fsub_rn(cv[c], m)); s = __fadd_rn(s, e[c]); }
#pragma unroll
    for (int c = 1; c < NCLS; c++) {
        float p  = __fdiv_rn(e[c], s);
        float sv = (p > 0.01f) ? p : -1.0f;
        g_umap[((size_t)b * NC1 + (c - 1)) * NA + n] = f2u(sv);
    }
}

// ============================================================================
// K2: per (b,cls) exact top-200: radix select over global row + bitonic sort
// grid: NB*NC1, 256 threads.  Shared ~10.5 KB -> high occupancy.
// ============================================================================
__global__ __launch_bounds__(256) void k_topk()
{
    __shared__ unsigned           s_hist[8][257];   // warp-private, bank-padded
    __shared__ unsigned long long s_cand[256];
    __shared__ unsigned           s_wsum[8];
    __shared__ unsigned           s_info[4];

    int task = blockIdx.x;
    int tid  = threadIdx.x;
    int wid  = tid >> 5, lane = tid & 31;

    const unsigned* urow = &g_umap[(size_t)task * NA];
    const uint4*    row4 = reinterpret_cast<const uint4*>(urow);   // NA/4 = 2183

    // ---- 4-level radix select ----
    unsigned prefix = 0, k = TK;
#pragma unroll
    for (int level = 0; level < 4; level++) {
        int shift = 24 - 8 * level;
        unsigned mask = (level == 0) ? 0u : (0xFFFFFFFFu << (32 - 8 * level));
        for (int i = tid; i < 8 * 257; i += 256) (&s_hist[0][0])[i] = 0;
        __syncthreads();
        for (int i = tid; i < NA / 4; i += 256) {
            uint4 q = row4[i];
            if ((q.x & mask) == prefix) atomicAdd(&s_hist[wid][(q.x >> shift) & 255], 1u);
            if ((q.y & mask) == prefix) atomicAdd(&s_hist[wid][(q.y >> shift) & 255], 1u);
            if ((q.z & mask) == prefix) atomicAdd(&s_hist[wid][(q.z >> shift) & 255], 1u);
            if ((q.w & mask) == prefix) atomicAdd(&s_hist[wid][(q.w >> shift) & 255], 1u);
        }
        __syncthreads();
        unsigned c = 0;
#pragma unroll
        for (int w = 0; w < 8; w++) c += s_hist[w][tid];
        // intra-warp inclusive suffix sum (bin tid ascending with lane)
        unsigned v = c;
#pragma unroll
        for (int off = 1; off < 32; off <<= 1) {
            unsigned t = __shfl_down_sync(0xffffffffu, v, off);
            if (lane < 32 - off) v += t;
        }
        if (lane == 0) s_wsum[wid] = v;
        __syncthreads();
        unsigned above = 0;
#pragma unroll
        for (int w = 0; w < 8; w++) if (w > wid) above += s_wsum[w];
        v += above;                       // count of values in bins >= tid
        unsigned excl = v - c;            // strictly above bin tid
        if (excl < k && v >= k) {
            s_info[0] = prefix | ((unsigned)tid << shift);
            s_info[1] = k - excl;
        }
        __syncthreads();
        prefix = s_info[0];
        k      = s_info[1];
    }
    unsigned ucut = prefix, keq = k;

    // ---- gather exactly 200 candidates (two passes over global row) ----
    if (tid == 0) { s_info[2] = 0; s_info[3] = 0; }
    __syncthreads();
    for (int i = tid; i < NA / 4; i += 256) {
        uint4 q = row4[i];
        unsigned base = 4u * i;
#pragma unroll
        for (int j = 0; j < 4; j++) {
            unsigned u = (j == 0) ? q.x : (j == 1) ? q.y : (j == 2) ? q.z : q.w;
            if (u > ucut) {
                unsigned p = atomicAdd(&s_info[2], 1u);
                s_cand[p] = ((unsigned long long)u << 32) | (0xFFFFFFFFu - (base + j));
            }
        }
    }
    __syncthreads();
    unsigned ngt = s_info[2];
    for (int i = tid; i < NA / 4; i += 256) {
        uint4 q = row4[i];
        unsigned base = 4u * i;
#pragma unroll
        for (int j = 0; j < 4; j++) {
            unsigned u = (j == 0) ? q.x : (j == 1) ? q.y : (j == 2) ? q.z : q.w;
            if (u == ucut) {
                unsigned p = atomicAdd(&s_info[3], 1u);
                if (p < keq)
                    s_cand[ngt + p] = ((unsigned long long)u << 32) | (0xFFFFFFFFu - (base + j));
            }
        }
    }
    __syncthreads();
    if (tid >= TK) s_cand[tid] = 0ULL;
    __syncthreads();

    // ---- bitonic sort 256 keys desc (value desc, index asc on ties) ----
    for (int kk = 2; kk <= 256; kk <<= 1) {
        for (int j = kk >> 1; j > 0; j >>= 1) {
            int ixj = tid ^ j;
            if (ixj > tid) {
                unsigned long long a = s_cand[tid], c2 = s_cand[ixj];
                bool dir = ((tid & kk) == 0);
                if ((a < c2) == dir) { s_cand[tid] = c2; s_cand[ixj] = a; }
            }
            __syncthreads();
        }
    }

    if (tid < TK) g_cand[task * TK + tid] = s_cand[tid];
}

// ============================================================================
// K3: per (b,cls): decode selected boxes, suppression bitmatrix, ffs sweep
// grid: NB*NC1, 256 threads.  Shared ~12 KB.
// ============================================================================
__global__ __launch_bounds__(256) void k_nms(const float* __restrict__ loc,
                                             const float* __restrict__ dbox)
{
    __shared__ unsigned s_mat[TK][8];      // suppression bits: row r, word w
    __shared__ float4   s_box[NCAP];
    __shared__ float    s_area[NCAP];
    __shared__ float    s_score[NCAP];
    __shared__ unsigned s_aw[8];

    int task = blockIdx.x;
    int b    = task / NC1;
    int tid  = threadIdx.x;
    int wid  = tid >> 5, lane = tid & 31;

    bool alive = false;
    if (tid < NCAP) {
        float v = 0.f;
        float4 bb = make_float4(0.f, 0.f, 0.f, 0.f);
        if (tid < TK) {
            unsigned long long key = g_cand[task * TK + tid];
            unsigned u = (unsigned)(key >> 32);
            int idx = (int)(0xFFFFFFFFu - (unsigned)key);
            v = u2f(u);
            float4 l = reinterpret_cast<const float4*>(loc)[b * NA + idx];
            float4 d = reinterpret_cast<const float4*>(dbox)[idx];
            float cx = __fadd_rn(d.x, __fmul_rn(__fmul_rn(l.x, 0.1f), d.z));
            float cy = __fadd_rn(d.y, __fmul_rn(__fmul_rn(l.y, 0.1f), d.w));
            float w  = __fmul_rn(d.z, expf(__fmul_rn(l.z, 0.2f)));
            float h  = __fmul_rn(d.w, expf(__fmul_rn(l.w, 0.2f)));
            float x1 = __fsub_rn(cx, __fmul_rn(w, 0.5f));
            float y1 = __fsub_rn(cy, __fmul_rn(h, 0.5f));
            float x2 = __fadd_rn(x1, w);
            float y2 = __fadd_rn(y1, h);
            bb.x = fminf(fmaxf(x1, 0.f), 1.f);
            bb.y = fminf(fmaxf(y1, 0.f), 1.f);
            bb.z = fminf(fmaxf(x2, 0.f), 1.f);
            bb.w = fminf(fmaxf(y2, 0.f), 1.f);
        }
        s_box[tid]   = bb;
        s_area[tid]  = __fmul_rn(__fsub_rn(bb.z, bb.x), __fsub_rn(bb.w, bb.y));
        s_score[tid] = v;
        alive = (v > 0.01f);       // tid>=TK has v=0 -> dead
    }
    unsigned ab = __ballot_sync(0xffffffffu, alive);
    if (lane == 0 && wid < 8) s_aw[wid] = (wid < 7) ? ab : 0u;
    __syncthreads();

    // ---- suppression bitmatrix: 872 (row,word) tasks over 8 warps ----
    for (int it = 0; it < 109; it++) {
        int t = wid + 8 * it;
        int w = (t >= 32) + (t >= 96) + (t >= 192) + (t >= 320) + (t >= 480) + (t >= 672);
        int base = (w == 0) ? 0 : (w == 1) ? 32 : (w == 2) ? 96 : (w == 3) ? 192
                 : (w == 4) ? 320 : (w == 5) ? 480 : 672;
        int r = t - base;
        int j = w * 32 + lane;
        float4 bj = s_box[j];  float aj = s_area[j];
        float4 br = s_box[r];  float ar = s_area[r];
        float xx1 = fmaxf(bj.x, br.x);
        float yy1 = fmaxf(bj.y, br.y);
        float xx2 = fminf(bj.z, br.z);
        float yy2 = fminf(bj.w, br.w);
        float iw = fmaxf(__fsub_rn(xx2, xx1), 0.f);
        float ih = fmaxf(__fsub_rn(yy2, yy1), 0.f);
        float inter = __fmul_rn(iw, ih);
        float denom = __fsub_rn(__fadd_rn(aj, ar), inter);
        float iou   = __fdiv_rn(inter, denom);          // IEEE; NaN -> suppress
        bool bit = (j > r) && (j < TK) && !(iou <= 0.45f);
        unsigned word = __ballot_sync(0xffffffffu, bit);
        if (lane == 0) s_mat[r][w] = word;
    }
    __syncthreads();

    // ---- greedy sweep: warp 0, all lanes redundant, visit alive bits only ----
    if (wid == 0) {
        unsigned a0 = s_aw[0], a1 = s_aw[1], a2 = s_aw[2], a3 = s_aw[3];
        unsigned a4 = s_aw[4], a5 = s_aw[5], a6 = s_aw[6];
#define SWEEP_WORD(S, AS, REST)                                        \
        { unsigned m = AS;                                             \
          while (m) {                                                  \
              int l = __ffs(m) - 1;                                    \
              const unsigned* row = s_mat[32 * (S) + l];               \
              AS &= ~row[S]; REST                                      \
              m = (l == 31) ? 0u : (AS & (~0u << (l + 1)));            \
          } }
        SWEEP_WORD(0, a0, a1&=~row[1];a2&=~row[2];a3&=~row[3];a4&=~row[4];a5&=~row[5];a6&=~row[6];)
        SWEEP_WORD(1, a1, a2&=~row[2];a3&=~row[3];a4&=~row[4];a5&=~row[5];a6&=~row[6];)
        SWEEP_WORD(2, a2, a3&=~row[3];a4&=~row[4];a5&=~row[5];a6&=~row[6];)
        SWEEP_WORD(3, a3, a4&=~row[4];a5&=~row[5];a6&=~row[6];)
        SWEEP_WORD(4, a4, a5&=~row[5];a6&=~row[6];)
        SWEEP_WORD(5, a5, a6&=~row[6];)
        SWEEP_WORD(6, a6, ;)
#undef SWEEP_WORD
        if (lane == 0) {
            s_aw[0]=a0; s_aw[1]=a1; s_aw[2]=a2; s_aw[3]=a3;
            s_aw[4]=a4; s_aw[5]=a5; s_aw[6]=a6;
        }
    }
    __syncthreads();

    if (tid < TK) {
        bool kp = (s_aw[tid >> 5] >> (tid & 31)) & 1;
        int o = task * TK + tid;
        g_kscore[o] = kp ? s_score[tid] : 0.f;
        g_kbox[o]   = kp ? s_box[tid]  : make_float4(0.f, 0.f, 0.f, 0.f);
    }
}

// ============================================================================
// K4: per batch: global top-200 over 4000 kept scores, per-class compaction
// ============================================================================
__global__ __launch_bounds__(256) void k_final(float* __restrict__ out)
{
    __shared__ unsigned long long s_key[4096];
    int b   = blockIdx.x;
    int tid = threadIdx.x;

    const float* ks = &g_kscore[b * NC1 * TK];
    for (int i = tid; i < 4096; i += 256) {
        unsigned long long key = 0ULL;
        if (i < NC1 * TK) {
            unsigned u = f2u(ks[i]);
            key = ((unsigned long long)u << 32) | (0xFFFFFFFFu - (unsigned)i);
        }
        s_key[i] = key;
    }
    float* ob = out + (size_t)b * NCLS * TK * 5;
    for (int i = tid; i < NCLS * TK * 5; i += 256) ob[i] = 0.f;
    __syncthreads();

    for (int kk = 2; kk <= 4096; kk <<= 1) {
        for (int j = kk >> 1; j > 0; j >>= 1) {
            for (int i = tid; i < 4096; i += 256) {
                int ixj = i ^ j;
                if (ixj > i) {
                    unsigned long long a = s_key[i], c2 = s_key[ixj];
                    bool dir = ((i & kk) == 0);
                    if ((a < c2) == dir) { s_key[i] = c2; s_key[ixj] = a; }
                }
            }
            __syncthreads();
        }
    }

    if (tid < TK) {
        unsigned long long key = s_key[tid];
        unsigned u = (unsigned)(key >> 32);
        if (u > 0x80000000u) {
            unsigned flat = 0xFFFFFFFFu - (unsigned)key;
            int cls = (int)(flat / TK);
            int pos = 0;
            for (int g = 0; g < tid; g++) {
                unsigned long long k2 = s_key[g];
                unsigned u2 = (unsigned)(k2 >> 32);
                if (u2 > 0x80000000u) {
                    unsigned f2 = 0xFFFFFFFFu - (unsigned)k2;
                    if ((int)(f2 / TK) == cls) pos++;
                }
            }
            float v   = __uint_as_float(u & 0x7FFFFFFFu);
            float4 bb = g_kbox[b * NC1 * TK + flat];
            float* row = ob + ((cls + 1) * TK + pos) * 5;
            row[0] = v;
            row[1] = bb.x; row[2] = bb.y; row[3] = bb.z; row[4] = bb.w;
        }
    }
}

// ============================================================================
extern "C" void kernel_launch(void* const* d_in, const int* in_sizes, int n_in,
                              void* d_out, int out_size)
{
    const float* loc  = (const float*)d_in[0];   // [B, N, 4]
    const float* conf = (const float*)d_in[1];   // [B, N, C]
    const float* dbox = (const float*)d_in[2];   // [N, 4]
    float* out = (float*)d_out;                  // [B, C, 200, 5]

    k_prep <<<dim3((NA + 255) / 256, NB), 256>>>(conf);
    k_topk <<<NB * NC1, 256>>>();
    k_nms  <<<NB * NC1, 256>>>(loc, dbox);
    k_final<<<NB, 256>>>(out);
}

// round 6
// speedup vs baseline: 1.0887x; 1.0003x over previous
#include <cuda_runtime.h>

// SSD post-processing, B=128, N=8732, C=21, top_k=keep_top_k=200.
// K1 k_prep : softmax -> order-mapped thresholded scores (g_umap)
// K2 k_topk : per-(b,cls) exact top-200 via 4-level radix select reading
//             global directly (L2-resident), bitonic sort -> g_cand
// K3 k_nms  : decode selected boxes + IoU suppression bitmatrix + ffs sweep
// K4 k_final: per-batch global top-200 + per-class compaction

#define NB   128
#define NA   8732
#define NCLS 21
#define NC1  20
#define TK   200
#define NCAP 224

__device__ unsigned int       g_umap[(size_t)NB * NC1 * NA];
__device__ unsigned long long g_cand[NB * NC1 * TK];
__device__ float              g_kscore[NB * NC1 * TK];
__device__ float4             g_kbox[NB * NC1 * TK];

__device__ __forceinline__ unsigned f2u(float f) {
    unsigned b = __float_as_uint(f);
    return (b & 0x80000000u) ? ~b : (b | 0x80000000u);
}
__device__ __forceinline__ float u2f(unsigned u) {
    unsigned b = (u & 0x80000000u) ? (u & 0x7FFFFFFFu) : ~u;
    return __uint_as_float(b);
}

// ============================================================================
// K1: softmax over 21 classes -> order-mapped thresholded scores
// ============================================================================
__global__ __launch_bounds__(256) void k_prep(const float* __restrict__ conf)
{
    __shared__ float s_conf[256 * NCLS];
    int b   = blockIdx.y;
    int n0  = blockIdx.x * 256;
    int tid = threadIdx.x;

    int nrow = NA - n0; if (nrow > 256) nrow = 256;
    int cnt  = nrow * NCLS;
    size_t base = ((size_t)b * NA + n0) * NCLS;
    for (int i = tid; i < cnt; i += 256) s_conf[i] = conf[base + i];
    __syncthreads();

    int n = n0 + tid;
    if (n >= NA) return;

    const float* cv = &s_conf[tid * NCLS];
    float m = cv[0];
#pragma unroll
    for (int c = 1; c < NCLS; c++) m = fmaxf(m, cv[c]);
    float e[NCLS];
    float s = 0.f;
#pragma unroll
    for (int c = 0; c < NCLS; c++) { e[c] = expf(__fsub_rn(cv[c], m)); s = __fadd_rn(s, e[c]); }
#pragma unroll
    for (int c = 1; c < NCLS; c++) {
        float p  = __fdiv_rn(e[c], s);
        float sv = (p > 0.01f) ? p : -1.0f;
        g_umap[((size_t)b * NC1 + (c - 1)) * NA + n] = f2u(sv);
    }
}

// ============================================================================
// K2: per (b,cls) exact top-200: radix select over global row + bitonic sort
// grid: NB*NC1, 256 threads.  Shared ~10.5 KB -> high occupancy.
// ============================================================================
__global__ __launch_bounds__(256) void k_topk()
{
    __shared__ unsigned           s_hist[8][257];   // warp-private, bank-padded
    __shared__ unsigned long long s_cand[256];
    __shared__ unsigned           s_wsum[8];
    __shared__ unsigned           s_info[4];

    int task = blockIdx.x;
    int tid  = threadIdx.x;
    int wid  = tid >> 5, lane = tid & 31;

    const unsigned* urow = &g_umap[(size_t)task * NA];
    const uint4*    row4 = reinterpret_cast<const uint4*>(urow);   // NA/4 = 2183

    // ---- 4-level radix select ----
    unsigned prefix = 0, k = TK;
#pragma unroll
    for (int level = 0; level < 4; level++) {
        int shift = 24 - 8 * level;
        unsigned mask = (level == 0) ? 0u : (0xFFFFFFFFu << (32 - 8 * level));
        for (int i = tid; i < 8 * 257; i += 256) (&s_hist[0][0])[i] = 0;
        __syncthreads();
        for (int i = tid; i < NA / 4; i += 256) {
            uint4 q = row4[i];
            if ((q.x & mask) == prefix) atomicAdd(&s_hist[wid][(q.x >> shift) & 255], 1u);
            if ((q.y & mask) == prefix) atomicAdd(&s_hist[wid][(q.y >> shift) & 255], 1u);
            if ((q.z & mask) == prefix) atomicAdd(&s_hist[wid][(q.z >> shift) & 255], 1u);
            if ((q.w & mask) == prefix) atomicAdd(&s_hist[wid][(q.w >> shift) & 255], 1u);
        }
        __syncthreads();
        unsigned c = 0;
#pragma unroll
        for (int w = 0; w < 8; w++) c += s_hist[w][tid];
        // intra-warp inclusive suffix sum (bin tid ascending with lane)
        unsigned v = c;
#pragma unroll
        for (int off = 1; off < 32; off <<= 1) {
            unsigned t = __shfl_down_sync(0xffffffffu, v, off);
            if (lane < 32 - off) v += t;
        }
        if (lane == 0) s_wsum[wid] = v;
        __syncthreads();
        unsigned above = 0;
#pragma unroll
        for (int w = 0; w < 8; w++) if (w > wid) above += s_wsum[w];
        v += above;                       // count of values in bins >= tid
        unsigned excl = v - c;            // strictly above bin tid
        if (excl < k && v >= k) {
            s_info[0] = prefix | ((unsigned)tid << shift);
            s_info[1] = k - excl;
        }
        __syncthreads();
        prefix = s_info[0];
        k      = s_info[1];
    }
    unsigned ucut = prefix, keq = k;

    // ---- gather exactly 200 candidates (two passes over global row) ----
    if (tid == 0) { s_info[2] = 0; s_info[3] = 0; }
    __syncthreads();
    for (int i = tid; i < NA / 4; i += 256) {
        uint4 q = row4[i];
        unsigned base = 4u * i;
#pragma unroll
        for (int j = 0; j < 4; j++) {
            unsigned u = (j == 0) ? q.x : (j == 1) ? q.y : (j == 2) ? q.z : q.w;
            if (u > ucut) {
                unsigned p = atomicAdd(&s_info[2], 1u);
                s_cand[p] = ((unsigned long long)u << 32) | (0xFFFFFFFFu - (base + j));
            }
        }
    }
    __syncthreads();
    unsigned ngt = s_info[2];
    for (int i = tid; i < NA / 4; i += 256) {
        uint4 q = row4[i];
        unsigned base = 4u * i;
#pragma unroll
        for (int j = 0; j < 4; j++) {
            unsigned u = (j == 0) ? q.x : (j == 1) ? q.y : (j == 2) ? q.z : q.w;
            if (u == ucut) {
                unsigned p = atomicAdd(&s_info[3], 1u);
                if (p < keq)
                    s_cand[ngt + p] = ((unsigned long long)u << 32) | (0xFFFFFFFFu - (base + j));
            }
        }
    }
    __syncthreads();
    if (tid >= TK) s_cand[tid] = 0ULL;
    __syncthreads();

    // ---- bitonic sort 256 keys desc (value desc, index asc on ties) ----
    for (int kk = 2; kk <= 256; kk <<= 1) {
        for (int j = kk >> 1; j > 0; j >>= 1) {
            int ixj = tid ^ j;
            if (ixj > tid) {
                unsigned long long a = s_cand[tid], c2 = s_cand[ixj];
                bool dir = ((tid & kk) == 0);
                if ((a < c2) == dir) { s_cand[tid] = c2; s_cand[ixj] = a; }
            }
            __syncthreads();
        }
    }

    if (tid < TK) g_cand[task * TK + tid] = s_cand[tid];
}

// ============================================================================
// K3: per (b,cls): decode selected boxes, suppression bitmatrix, ffs sweep
// grid: NB*NC1, 256 threads.  Shared ~12 KB.
// ============================================================================
__global__ __launch_bounds__(256) void k_nms(const float* __restrict__ loc,
                                             const float* __restrict__ dbox)
{
    __shared__ unsigned s_mat[TK][8];      // suppression bits: row r, word w
    __shared__ float4   s_box[NCAP];
    __shared__ float    s_area[NCAP];
    __shared__ float    s_score[NCAP];
    __shared__ unsigned s_aw[8];

    int task = blockIdx.x;
    int b    = task / NC1;
    int tid  = threadIdx.x;
    int wid  = tid >> 5, lane = tid & 31;

    bool alive = false;
    if (tid < NCAP) {
        float v = 0.f;
        float4 bb = make_float4(0.f, 0.f, 0.f, 0.f);
        if (tid < TK) {
            unsigned long long key = g_cand[task * TK + tid];
            unsigned u = (unsigned)(key >> 32);
            int idx = (int)(0xFFFFFFFFu - (unsigned)key);
            v = u2f(u);
            float4 l = reinterpret_cast<const float4*>(loc)[b * NA + idx];
            float4 d = reinterpret_cast<const float4*>(dbox)[idx];
            float cx = __fadd_rn(d.x, __fmul_rn(__fmul_rn(l.x, 0.1f), d.z));
            float cy = __fadd_rn(d.y, __fmul_rn(__fmul_rn(l.y, 0.1f), d.w));
            float w  = __fmul_rn(d.z, expf(__fmul_rn(l.z, 0.2f)));
            float h  = __fmul_rn(d.w, expf(__fmul_rn(l.w, 0.2f)));
            float x1 = __fsub_rn(cx, __fmul_rn(w, 0.5f));
            float y1 = __fsub_rn(cy, __fmul_rn(h, 0.5f));
            float x2 = __fadd_rn(x1, w);
            float y2 = __fadd_rn(y1, h);
            bb.x = fminf(fmaxf(x1, 0.f), 1.f);
            bb.y = fminf(fmaxf(y1, 0.f), 1.f);
            bb.z = fminf(fmaxf(x2, 0.f), 1.f);
            bb.w = fminf(fmaxf(y2, 0.f), 1.f);
        }
        s_box[tid]   = bb;
        s_area[tid]  = __fmul_rn(__fsub_rn(bb.z, bb.x), __fsub_rn(bb.w, bb.y));
        s_score[tid] = v;
        alive = (v > 0.01f);       // tid>=TK has v=0 -> dead
    }
    unsigned ab = __ballot_sync(0xffffffffu, alive);
    if (lane == 0 && wid < 8) s_aw[wid] = (wid < 7) ? ab : 0u;
    __syncthreads();

    // ---- suppression bitmatrix: 872 (row,word) tasks over 8 warps ----
    for (int it = 0; it < 109; it++) {
        int t = wid + 8 * it;
        int w = (t >= 32) + (t >= 96) + (t >= 192) + (t >= 320) + (t >= 480) + (t >= 672);
        int base = (w == 0) ? 0 : (w == 1) ? 32 : (w == 2) ? 96 : (w == 3) ? 192
                 : (w == 4) ? 320 : (w == 5) ? 480 : 672;
        int r = t - base;
        int j = w * 32 + lane;
        float4 bj = s_box[j];  float aj = s_area[j];
        float4 br = s_box[r];  float ar = s_area[r];
        float xx1 = fmaxf(bj.x, br.x);
        float yy1 = fmaxf(bj.y, br.y);
        float xx2 = fminf(bj.z, br.z);
        float yy2 = fminf(bj.w, br.w);
        float iw = fmaxf(__fsub_rn(xx2, xx1), 0.f);
        float ih = fmaxf(__fsub_rn(yy2, yy1), 0.f);
        float inter = __fmul_rn(iw, ih);
        float denom = __fsub_rn(__fadd_rn(aj, ar), inter);
        float iou   = __fdiv_rn(inter, denom);          // IEEE; NaN -> suppress
        bool bit = (j > r) && (j < TK) && !(iou <= 0.45f);
        unsigned word = __ballot_sync(0xffffffffu, bit);
        if (lane == 0) s_mat[r][w] = word;
    }
    __syncthreads();

    // ---- greedy sweep: warp 0, all lanes redundant, visit alive bits only ----
    if (wid == 0) {
        unsigned a0 = s_aw[0], a1 = s_aw[1], a2 = s_aw[2], a3 = s_aw[3];
        unsigned a4 = s_aw[4], a5 = s_aw[5], a6 = s_aw[6];
#define SWEEP_WORD(S, AS, REST)                                        \
        { unsigned m = AS;                                             \
          while (m) {                                                  \
              int l = __ffs(m) - 1;                                    \
              const unsigned* row = s_mat[32 * (S) + l];               \
              AS &= ~row[S]; REST                                      \
              m = (l == 31) ? 0u : (AS & (~0u << (l + 1)));            \
          } }
        SWEEP_WORD(0, a0, a1&=~row[1];a2&=~row[2];a3&=~row[3];a4&=~row[4];a5&=~row[5];a6&=~row[6];)
        SWEEP_WORD(1, a1, a2&=~row[2];a3&=~row[3];a4&=~row[4];a5&=~row[5];a6&=~row[6];)
        SWEEP_WORD(2, a2, a3&=~row[3];a4&=~row[4];a5&=~row[5];a6&=~row[6];)
        SWEEP_WORD(3, a3, a4&=~row[4];a5&=~row[5];a6&=~row[6];)
        SWEEP_WORD(4, a4, a5&=~row[5];a6&=~row[6];)
        SWEEP_WORD(5, a5, a6&=~row[6];)
        SWEEP_WORD(6, a6, ;)
#undef SWEEP_WORD
        if (lane == 0) {
            s_aw[0]=a0; s_aw[1]=a1; s_aw[2]=a2; s_aw[3]=a3;
            s_aw[4]=a4; s_aw[5]=a5; s_aw[6]=a6;
        }
    }
    __syncthreads();

    if (tid < TK) {
        bool kp = (s_aw[tid >> 5] >> (tid & 31)) & 1;
        int o = task * TK + tid;
        g_kscore[o] = kp ? s_score[tid] : 0.f;
        g_kbox[o]   = kp ? s_box[tid]  : make_float4(0.f, 0.f, 0.f, 0.f);
    }
}

// ============================================================================
// K4: per batch: global top-200 over 4000 kept scores, per-class compaction
// ============================================================================
__global__ __launch_bounds__(256) void k_final(float* __restrict__ out)
{
    __shared__ unsigned long long s_key[4096];
    int b   = blockIdx.x;
    int tid = threadIdx.x;

    const float* ks = &g_kscore[b * NC1 * TK];
    for (int i = tid; i < 4096; i += 256) {
        unsigned long long key = 0ULL;
        if (i < NC1 * TK) {
            unsigned u = f2u(ks[i]);
            key = ((unsigned long long)u << 32) | (0xFFFFFFFFu - (unsigned)i);
        }
        s_key[i] = key;
    }
    float* ob = out + (size_t)b * NCLS * TK * 5;
    for (int i = tid; i < NCLS * TK * 5; i += 256) ob[i] = 0.f;
    __syncthreads();

    for (int kk = 2; kk <= 4096; kk <<= 1) {
        for (int j = kk >> 1; j > 0; j >>= 1) {
            for (int i = tid; i < 4096; i += 256) {
                int ixj = i ^ j;
                if (ixj > i) {
                    unsigned long long a = s_key[i], c2 = s_key[ixj];
                    bool dir = ((i & kk) == 0);
                    if ((a < c2) == dir) { s_key[i] = c2; s_key[ixj] = a; }
                }
            }
            __syncthreads();
        }
    }

    if (tid < TK) {
        unsigned long long key = s_key[tid];
        unsigned u = (unsigned)(key >> 32);
        if (u > 0x80000000u) {
            unsigned flat = 0xFFFFFFFFu - (unsigned)key;
            int cls = (int)(flat / TK);
            int pos = 0;
            for (int g = 0; g < tid; g++) {
                unsigned long long k2 = s_key[g];
                unsigned u2 = (unsigned)(k2 >> 32);
                if (u2 > 0x80000000u) {
                    unsigned f2 = 0xFFFFFFFFu - (unsigned)k2;
                    if ((int)(f2 / TK) == cls) pos++;
                }
            }
            float v   = __uint_as_float(u & 0x7FFFFFFFu);
            float4 bb = g_kbox[b * NC1 * TK + flat];
            float* row = ob + ((cls + 1) * TK + pos) * 5;
            row[0] = v;
            row[1] = bb.x; row[2] = bb.y; row[3] = bb.z; row[4] = bb.w;
        }
    }
}

// ============================================================================
extern "C" void kernel_launch(void* const* d_in, const int* in_sizes, int n_in,
                              void* d_out, int out_size)
{
    const float* loc  = (const float*)d_in[0];   // [B, N, 4]
    const float* conf = (const float*)d_in[1];   // [B, N, C]
    const float* dbox = (const float*)d_in[2];   // [N, 4]
    float* out = (float*)d_out;                  // [B, C, 200, 5]

    k_prep <<<dim3((NA + 255) / 256, NB), 256>>>(conf);
    k_topk <<<NB * NC1, 256>>>();
    k_nms  <<<NB * NC1, 256>>>(loc, dbox);
    k_final<<<NB, 256>>>(out);
}